// round 2
// baseline (speedup 1.0000x reference)
#include <cuda_runtime.h>

// Sinkhorn transport-plan kernel.
// L=64 layers, B=7 bit options, 200 iterations, EPS=0.02.
// Inputs (metadata order): theta [64,7] f32, phi [7] f32, n [64] f32,
//                          sens [64] f32, err [7] f32.
// Output: P [64,7] f32 (normalized to sum 1).
//
// Single warp; lane r owns rows r and r+32 in registers. Row logsumexp is
// in-lane; column logsumexp is a 5-level butterfly over the warp with the
// 7 columns fully unrolled so the shuffle chains pipeline.

#define LL 64
#define BB 7
#define NITER 200

__global__ __launch_bounds__(32, 1)
void sinkhorn_kernel(const float* __restrict__ theta,
                     const float* __restrict__ phi,
                     const float* __restrict__ nbuf,
                     const float* __restrict__ sens,
                     const float* __restrict__ err,
                     float* __restrict__ out)
{
    const unsigned FULL = 0xffffffffu;
    const int lane = threadIdx.x;
    const int r0 = lane, r1 = lane + 32;
    const float inv_eps = 50.0f;   // 1 / 0.02
    const float TINY = 1e-40f;

    // ---- load inputs ----
    float n0 = nbuf[r0], n1 = nbuf[r1];
    float se0 = sens[r0], se1 = sens[r1];

    float ev[BB], pv[BB];
    #pragma unroll
    for (int j = 0; j < BB; ++j) { ev[j] = err[j]; pv[j] = phi[j]; }

    // ---- a = n / sum(n); log_a ----
    float sn = n0 + n1;
    #pragma unroll
    for (int o = 16; o > 0; o >>= 1) sn += __shfl_xor_sync(FULL, sn, o);
    float log_a0 = __logf(n0 / sn + TINY);
    float log_a1 = __logf(n1 / sn + TINY);

    // ---- b = softmax(phi); log_b (replicated per lane) ----
    float pm = pv[0];
    #pragma unroll
    for (int j = 1; j < BB; ++j) pm = fmaxf(pm, pv[j]);
    float ps = 0.f, pe[BB];
    #pragma unroll
    for (int j = 0; j < BB; ++j) { pe[j] = __expf(pv[j] - pm); ps += pe[j]; }
    float inv_ps = 1.0f / ps;
    float log_b[BB];
    #pragma unroll
    for (int j = 0; j < BB; ++j) log_b[j] = __logf(pe[j] * inv_ps + TINY);

    // ---- K = (theta - C) / EPS,  C = (n*sens) * err ----
    float c0 = n0 * se0, c1 = n1 * se1;
    float K0[BB], K1[BB];
    #pragma unroll
    for (int j = 0; j < BB; ++j) {
        K0[j] = (theta[r0 * BB + j] - c0 * ev[j]) * inv_eps;
        K1[j] = (theta[r1 * BB + j] - c1 * ev[j]) * inv_eps;
    }

    // ---- Sinkhorn iterations ----
    float f0 = 0.f, f1 = 0.f, g[BB];
    #pragma unroll
    for (int j = 0; j < BB; ++j) g[j] = 0.f;

    for (int it = 0; it < NITER; ++it) {
        // f = log_a - logsumexp_j(K + g)   (in-lane, 7 elems per row)
        float t0[BB], t1[BB];
        float m0 = -3.4e38f, m1 = -3.4e38f;
        #pragma unroll
        for (int j = 0; j < BB; ++j) {
            t0[j] = K0[j] + g[j];
            t1[j] = K1[j] + g[j];
            m0 = fmaxf(m0, t0[j]);
            m1 = fmaxf(m1, t1[j]);
        }
        float s0 = 0.f, s1 = 0.f;
        #pragma unroll
        for (int j = 0; j < BB; ++j) {
            s0 += __expf(t0[j] - m0);
            s1 += __expf(t1[j] - m1);
        }
        f0 = log_a0 - (m0 + __logf(s0));
        f1 = log_a1 - (m1 + __logf(s1));

        // g = log_b - logsumexp_i(K + f)   (64 rows = 2/lane x 32 lanes)
        float v0[BB], v1[BB], m[BB];
        #pragma unroll
        for (int j = 0; j < BB; ++j) {
            v0[j] = K0[j] + f0;
            v1[j] = K1[j] + f1;
            m[j] = fmaxf(v0[j], v1[j]);
        }
        #pragma unroll
        for (int o = 16; o > 0; o >>= 1) {
            #pragma unroll
            for (int j = 0; j < BB; ++j)
                m[j] = fmaxf(m[j], __shfl_xor_sync(FULL, m[j], o));
        }
        float s[BB];
        #pragma unroll
        for (int j = 0; j < BB; ++j)
            s[j] = __expf(v0[j] - m[j]) + __expf(v1[j] - m[j]);
        #pragma unroll
        for (int o = 16; o > 0; o >>= 1) {
            #pragma unroll
            for (int j = 0; j < BB; ++j)
                s[j] += __shfl_xor_sync(FULL, s[j], o);
        }
        #pragma unroll
        for (int j = 0; j < BB; ++j)
            g[j] = log_b[j] - (m[j] + __logf(s[j]));
    }

    // ---- P = exp(K + f + g); normalize by global sum + TINY ----
    float P0[BB], P1[BB];
    float psum = 0.f;
    #pragma unroll
    for (int j = 0; j < BB; ++j) {
        P0[j] = __expf(K0[j] + f0 + g[j]);
        P1[j] = __expf(K1[j] + f1 + g[j]);
        psum += P0[j] + P1[j];
    }
    #pragma unroll
    for (int o = 16; o > 0; o >>= 1) psum += __shfl_xor_sync(FULL, psum, o);
    float inv = 1.0f / (psum + TINY);
    #pragma unroll
    for (int j = 0; j < BB; ++j) {
        out[r0 * BB + j] = P0[j] * inv;
        out[r1 * BB + j] = P1[j] * inv;
    }
}

extern "C" void kernel_launch(void* const* d_in, const int* in_sizes, int n_in,
                              void* d_out, int out_size) {
    const float* theta = (const float*)d_in[0];
    const float* phi   = (const float*)d_in[1];
    const float* n     = (const float*)d_in[2];
    const float* sens  = (const float*)d_in[3];
    const float* err   = (const float*)d_in[4];
    float* out = (float*)d_out;
    sinkhorn_kernel<<<1, 32>>>(theta, phi, n, sens, err, out);
}

// round 9
// speedup vs baseline: 1.4465x; 1.4465x over previous
#include <cuda_runtime.h>

// Sinkhorn transport plan, L=64, B=7, 200 iterations, EPS=0.02.
// Log2-domain throughout (linear domain underflows: verified R3 failure).
//
// Single warp, lane r owns rows r and r+32 in registers.
//   f-update: in-lane logsumexp over 7 (max tree + ex2 + sum tree + lg2)
//   g-update: column logsumexp over 64 rows:
//       exact column max via __reduce_max_sync on order-preserving s32 keys
//       (redux.f32 doesn't exist on sm_103; s32 redux does), then ex2 and a
//       5-level shuffle-add butterfly for the sum, then lg2.
// All transcendentals are raw MUFU ex2/lg2.approx; log2(e)/EPS folded into K.

#define BB 7
#define NITER 200

__device__ __forceinline__ float ex2(float x) {
    float y; asm("ex2.approx.ftz.f32 %0, %1;" : "=f"(y) : "f"(x)); return y;
}
__device__ __forceinline__ float lg2(float x) {
    float y; asm("lg2.approx.ftz.f32 %0, %1;" : "=f"(y) : "f"(x)); return y;
}
// Exact warp-wide float max via s32 redux with a monotonic key transform.
// k = b ^ ((b>>31) & 0x7fffffff) is order-preserving (signed) and self-inverse.
__device__ __forceinline__ float warp_max(float x) {
    int b = __float_as_int(x);
    int k = b ^ ((b >> 31) & 0x7fffffff);
    int r = __reduce_max_sync(0xffffffffu, k);
    return __int_as_float(r ^ ((r >> 31) & 0x7fffffff));
}

__global__ __launch_bounds__(32, 1)
void sinkhorn_kernel(const float* __restrict__ theta,
                     const float* __restrict__ phi,
                     const float* __restrict__ nbuf,
                     const float* __restrict__ sens,
                     const float* __restrict__ err,
                     float* __restrict__ out)
{
    const unsigned FULL = 0xffffffffu;
    const int lane = threadIdx.x;
    const int r0 = lane, r1 = lane + 32;
    const float TINY = 1e-40f;
    const float L2E = 1.4426950408889634f;     // log2(e)
    const float SCALE = 72.13475204444817f;    // log2(e)/EPS

    // ---- load inputs ----
    float n0 = nbuf[r0], n1 = nbuf[r1];
    float se0 = sens[r0], se1 = sens[r1];
    float ev[BB], pv[BB];
    #pragma unroll
    for (int j = 0; j < BB; ++j) { ev[j] = err[j]; pv[j] = phi[j]; }

    // ---- a = n / sum(n); log2 a ----
    float sn = n0 + n1;
    #pragma unroll
    for (int o = 16; o > 0; o >>= 1) sn += __shfl_xor_sync(FULL, sn, o);
    float la0 = lg2(n0 / sn + TINY);
    float la1 = lg2(n1 / sn + TINY);

    // ---- b = softmax(phi); log2 b (replicated per lane) ----
    float pm = pv[0];
    #pragma unroll
    for (int j = 1; j < BB; ++j) pm = fmaxf(pm, pv[j]);
    float ps = 0.f, pe[BB];
    #pragma unroll
    for (int j = 0; j < BB; ++j) { pe[j] = ex2((pv[j] - pm) * L2E); ps += pe[j]; }
    float inv_ps = 1.0f / ps;
    float lb2[BB];
    #pragma unroll
    for (int j = 0; j < BB; ++j) lb2[j] = lg2(pe[j] * inv_ps + TINY);

    // ---- K2 = (theta - n*sens*err) * log2(e)/EPS ----
    float c0 = n0 * se0, c1 = n1 * se1;
    float K20[BB], K21[BB];
    #pragma unroll
    for (int j = 0; j < BB; ++j) {
        K20[j] = (theta[r0 * BB + j] - c0 * ev[j]) * SCALE;
        K21[j] = (theta[r1 * BB + j] - c1 * ev[j]) * SCALE;
    }

    // ---- Sinkhorn iterations (log2 domain, exact stabilization) ----
    float F0 = 0.f, F1 = 0.f, G[BB];
    #pragma unroll
    for (int j = 0; j < BB; ++j) G[j] = 0.f;

    #pragma unroll 1
    for (int it = 0; it < NITER; ++it) {
        // f = la - log2sumexp2_j(K2 + G)   (in-lane, 7 per row)
        float t0[BB], t1[BB];
        #pragma unroll
        for (int j = 0; j < BB; ++j) {
            t0[j] = K20[j] + G[j];
            t1[j] = K21[j] + G[j];
        }
        float m0 = fmaxf(fmaxf(fmaxf(t0[0], t0[1]), fmaxf(t0[2], t0[3])),
                         fmaxf(fmaxf(t0[4], t0[5]), t0[6]));
        float m1 = fmaxf(fmaxf(fmaxf(t1[0], t1[1]), fmaxf(t1[2], t1[3])),
                         fmaxf(fmaxf(t1[4], t1[5]), t1[6]));
        float e0[BB], e1[BB];
        #pragma unroll
        for (int j = 0; j < BB; ++j) {
            e0[j] = ex2(t0[j] - m0);
            e1[j] = ex2(t1[j] - m1);
        }
        float s0 = ((e0[0] + e0[1]) + (e0[2] + e0[3])) + ((e0[4] + e0[5]) + e0[6]);
        float s1 = ((e1[0] + e1[1]) + (e1[2] + e1[3])) + ((e1[4] + e1[5]) + e1[6]);
        F0 = la0 - (m0 + lg2(s0));
        F1 = la1 - (m1 + lg2(s1));

        // g = lb - log2sumexp2_i(K2 + F)   (column reduction over the warp)
        float v0[BB], v1[BB], mm[BB];
        #pragma unroll
        for (int j = 0; j < BB; ++j) {
            v0[j] = K20[j] + F0;
            v1[j] = K21[j] + F1;
            mm[j] = warp_max(fmaxf(v0[j], v1[j]));   // exact column max, 1 level
        }
        float s[BB];
        #pragma unroll
        for (int j = 0; j < BB; ++j)
            s[j] = ex2(v0[j] - mm[j]) + ex2(v1[j] - mm[j]);
        #pragma unroll
        for (int o = 16; o > 0; o >>= 1) {
            #pragma unroll
            for (int j = 0; j < BB; ++j)
                s[j] += __shfl_xor_sync(FULL, s[j], o);
        }
        #pragma unroll
        for (int j = 0; j < BB; ++j)
            G[j] = lb2[j] - (mm[j] + lg2(s[j]));
    }

    // ---- P = exp2(K2 + F + G); normalize by global sum + TINY ----
    float P0[BB], P1[BB];
    float psum = 0.f;
    #pragma unroll
    for (int j = 0; j < BB; ++j) {
        P0[j] = ex2(K20[j] + F0 + G[j]);
        P1[j] = ex2(K21[j] + F1 + G[j]);
        psum += P0[j] + P1[j];
    }
    #pragma unroll
    for (int o = 16; o > 0; o >>= 1) psum += __shfl_xor_sync(FULL, psum, o);
    float inv = 1.0f / (psum + TINY);
    #pragma unroll
    for (int j = 0; j < BB; ++j) {
        out[r0 * BB + j] = P0[j] * inv;
        out[r1 * BB + j] = P1[j] * inv;
    }
}

extern "C" void kernel_launch(void* const* d_in, const int* in_sizes, int n_in,
                              void* d_out, int out_size) {
    const float* theta = (const float*)d_in[0];
    const float* phi   = (const float*)d_in[1];
    const float* n     = (const float*)d_in[2];
    const float* sens  = (const float*)d_in[3];
    const float* err   = (const float*)d_in[4];
    sinkhorn_kernel<<<1, 32>>>(theta, phi, n, sens, err, (float*)d_out);
}